// round 2
// baseline (speedup 1.0000x reference)
#include <cuda_runtime.h>
#include <math.h>

// Problem constants
#define B_    2
#define N_    2048
#define T_    2048
#define HID_  1024
#define HEADS_ 16
#define DH_   64
#define HALF_ 32
#define LAMBDA_INIT_ 0.8f

// Scratch for Q, K, V projections (16 MB each). __device__ globals: allowed scratch.
__device__ float g_q[(size_t)B_ * T_ * HID_];
__device__ float g_k[(size_t)B_ * N_ * HID_];
__device__ float g_v[(size_t)B_ * N_ * HID_];

// ---------------------------------------------------------------------------
// GEMM: C[M,1024] = X[M,1024] @ W[1024,1024]^T   (W row-major [out, in])
// Tile 64x64x16, 256 threads, 4x4 microtile.
// which: 0 -> g_q, 1 -> g_k, 2 -> g_v
// ---------------------------------------------------------------------------
__global__ __launch_bounds__(256) void gemm_xwT_kernel(
    const float* __restrict__ X, const float* __restrict__ W, int which)
{
    __shared__ float Xs[16][68];   // [k][m], padded stride 68
    __shared__ float Ws[16][68];   // [k][o]

    float* __restrict__ C = (which == 0) ? g_q : (which == 1) ? g_k : g_v;

    const int tid = threadIdx.x;
    const int tx = tid & 15;        // output-col group
    const int ty = tid >> 4;        // output-row group
    const int m0 = blockIdx.y * 64;
    const int o0 = blockIdx.x * 64;

    const int lrow = tid >> 2;          // 0..63  (row within tile for loads)
    const int lk4  = (tid & 3) << 2;    // 0,4,8,12 (k offset, float4)

    float acc[4][4] = {};

    for (int k0 = 0; k0 < 1024; k0 += 16) {
        float4 xa = *(const float4*)&X[(size_t)(m0 + lrow) * 1024 + k0 + lk4];
        float4 wa = *(const float4*)&W[(size_t)(o0 + lrow) * 1024 + k0 + lk4];
        __syncthreads();   // previous iteration's reads complete
        Xs[lk4 + 0][lrow] = xa.x;
        Xs[lk4 + 1][lrow] = xa.y;
        Xs[lk4 + 2][lrow] = xa.z;
        Xs[lk4 + 3][lrow] = xa.w;
        Ws[lk4 + 0][lrow] = wa.x;
        Ws[lk4 + 1][lrow] = wa.y;
        Ws[lk4 + 2][lrow] = wa.z;
        Ws[lk4 + 3][lrow] = wa.w;
        __syncthreads();

        #pragma unroll
        for (int kk = 0; kk < 16; kk++) {
            float4 a = *(const float4*)&Xs[kk][ty << 2];
            float4 b = *(const float4*)&Ws[kk][tx << 2];
            acc[0][0] += a.x * b.x; acc[0][1] += a.x * b.y; acc[0][2] += a.x * b.z; acc[0][3] += a.x * b.w;
            acc[1][0] += a.y * b.x; acc[1][1] += a.y * b.y; acc[1][2] += a.y * b.z; acc[1][3] += a.y * b.w;
            acc[2][0] += a.z * b.x; acc[2][1] += a.z * b.y; acc[2][2] += a.z * b.z; acc[2][3] += a.z * b.w;
            acc[3][0] += a.w * b.x; acc[3][1] += a.w * b.y; acc[3][2] += a.w * b.z; acc[3][3] += a.w * b.w;
        }
    }

    #pragma unroll
    for (int i = 0; i < 4; i++) {
        float4 r = make_float4(acc[i][0], acc[i][1], acc[i][2], acc[i][3]);
        *(float4*)&C[(size_t)(m0 + (ty << 2) + i) * 1024 + o0 + (tx << 2)] = r;
    }
}

// ---------------------------------------------------------------------------
// Differential flash attention.
// Grid: (T/64, HEADS, B). Block: 256 threads (16x16), 4x4 microtiles.
// Per head h: q1/k1 = channels [h*64, h*64+32), q2/k2 = [h*64+32, h*64+64),
// v = channels [h*64, h*64+64).
// out[b][t][h*64+d] = sum_n (att1 - lam*att2)[t][n] * v[n][d]
// with att1/att2 softmaxed independently (online, two states).
// ---------------------------------------------------------------------------

// smem float offsets
#define SM_QS   0              // [64][68]  channel-major (Qs[c*68 + t]), pre-scaled
#define SM_KS   4352           // [64][68]  channel-major
#define SM_VS   8704           // [64][64]  row-major (Vs[n*64 + d])
#define SM_P1   12800          // [64][64]
#define SM_P2   16896          // [64][64]
#define SM_LAM  20992
#define SM_FLOATS 20996

__device__ __forceinline__ void rank1_update(float (&s)[4][4], const float4 a, const float4 b) {
    s[0][0] += a.x * b.x; s[0][1] += a.x * b.y; s[0][2] += a.x * b.z; s[0][3] += a.x * b.w;
    s[1][0] += a.y * b.x; s[1][1] += a.y * b.y; s[1][2] += a.y * b.z; s[1][3] += a.y * b.w;
    s[2][0] += a.z * b.x; s[2][1] += a.z * b.y; s[2][2] += a.z * b.z; s[2][3] += a.z * b.w;
    s[3][0] += a.w * b.x; s[3][1] += a.w * b.y; s[3][2] += a.w * b.z; s[3][3] += a.w * b.w;
}

__global__ __launch_bounds__(256, 2) void diff_attn_kernel(
    const float* __restrict__ lq1, const float* __restrict__ lq2,
    const float* __restrict__ lk1, const float* __restrict__ lk2,
    float* __restrict__ out)
{
    extern __shared__ float sm[];
    float* Qs = sm + SM_QS;
    float* Ks = sm + SM_KS;
    float* Vs = sm + SM_VS;
    float* P1 = sm + SM_P1;
    float* P2 = sm + SM_P2;

    const int tid = threadIdx.x;
    const int tx = tid & 15;      // owns n cols / d dims tx*4..+3
    const int ty = tid >> 4;      // owns t rows ty*4..+3
    const int t0 = blockIdx.x * 64;
    const int h  = blockIdx.y;
    const int b  = blockIdx.z;

    if (tid == 0) {
        float s1 = 0.f, s2 = 0.f;
        #pragma unroll
        for (int i = 0; i < HALF_; i++) {
            s1 += lq1[i] * lk1[i];
            s2 += lq2[i] * lk2[i];
        }
        sm[SM_LAM] = expf(s1) - expf(s2) + LAMBDA_INIT_;
    }

    const float scale = 0.17677669529663687f;   // 1/sqrt(32)

    // Load Q tile (64 t x 64 c), channel-major, pre-scaled.
    {
        const float* qb = g_q + ((size_t)(b * T_ + t0)) * HID_ + h * 64;
        #pragma unroll
        for (int idx = tid; idx < 1024; idx += 256) {
            int t  = idx >> 4;
            int c4 = (idx & 15) << 2;
            float4 v = *(const float4*)&qb[(size_t)t * HID_ + c4];
            Qs[(c4 + 0) * 68 + t] = v.x * scale;
            Qs[(c4 + 1) * 68 + t] = v.y * scale;
            Qs[(c4 + 2) * 68 + t] = v.z * scale;
            Qs[(c4 + 3) * 68 + t] = v.w * scale;
        }
    }

    float m1[4], l1[4], m2[4], l2[4];
    float acc1[4][4] = {}, acc2[4][4] = {};
    #pragma unroll
    for (int i = 0; i < 4; i++) { m1[i] = -1e30f; m2[i] = -1e30f; l1[i] = 0.f; l2[i] = 0.f; }

    for (int nt = 0; nt < N_ / 64; nt++) {
        // --- load K (channel-major) and V (row-major) tiles ---
        const float* kb = g_k + ((size_t)(b * N_ + nt * 64)) * HID_ + h * 64;
        const float* vb = g_v + ((size_t)(b * N_ + nt * 64)) * HID_ + h * 64;
        #pragma unroll
        for (int idx = tid; idx < 1024; idx += 256) {
            int n  = idx >> 4;
            int c4 = (idx & 15) << 2;
            float4 kv = *(const float4*)&kb[(size_t)n * HID_ + c4];
            Ks[(c4 + 0) * 68 + n] = kv.x;
            Ks[(c4 + 1) * 68 + n] = kv.y;
            Ks[(c4 + 2) * 68 + n] = kv.z;
            Ks[(c4 + 3) * 68 + n] = kv.w;
            float4 vv = *(const float4*)&vb[(size_t)n * HID_ + c4];
            *(float4*)&Vs[n * 64 + c4] = vv;
        }
        __syncthreads();

        // --- scores: s1 = q1.k1, s2 = q2.k2 (4x4 each) ---
        float s1v[4][4] = {}, s2v[4][4] = {};
        #pragma unroll 8
        for (int d = 0; d < 32; d++) {
            float4 a1 = *(const float4*)&Qs[d * 68 + (ty << 2)];
            float4 b1 = *(const float4*)&Ks[d * 68 + (tx << 2)];
            rank1_update(s1v, a1, b1);
            float4 a2 = *(const float4*)&Qs[(d + 32) * 68 + (ty << 2)];
            float4 b2 = *(const float4*)&Ks[(d + 32) * 68 + (tx << 2)];
            rank1_update(s2v, a2, b2);
        }

        // --- online softmax update (per row, per half) ---
        #pragma unroll
        for (int i = 0; i < 4; i++) {
            // half 1
            {
                float mx = fmaxf(fmaxf(s1v[i][0], s1v[i][1]), fmaxf(s1v[i][2], s1v[i][3]));
                mx = fmaxf(mx, __shfl_xor_sync(0xffffffffu, mx, 8, 16));
                mx = fmaxf(mx, __shfl_xor_sync(0xffffffffu, mx, 4, 16));
                mx = fmaxf(mx, __shfl_xor_sync(0xffffffffu, mx, 2, 16));
                mx = fmaxf(mx, __shfl_xor_sync(0xffffffffu, mx, 1, 16));
                float mn = fmaxf(m1[i], mx);
                float sc = __expf(m1[i] - mn);
                m1[i] = mn;
                float rs = 0.f;
                #pragma unroll
                for (int j = 0; j < 4; j++) {
                    float p = __expf(s1v[i][j] - mn);
                    s1v[i][j] = p;
                    rs += p;
                }
                rs += __shfl_xor_sync(0xffffffffu, rs, 8, 16);
                rs += __shfl_xor_sync(0xffffffffu, rs, 4, 16);
                rs += __shfl_xor_sync(0xffffffffu, rs, 2, 16);
                rs += __shfl_xor_sync(0xffffffffu, rs, 1, 16);
                l1[i] = l1[i] * sc + rs;
                acc1[i][0] *= sc; acc1[i][1] *= sc; acc1[i][2] *= sc; acc1[i][3] *= sc;
            }
            // half 2
            {
                float mx = fmaxf(fmaxf(s2v[i][0], s2v[i][1]), fmaxf(s2v[i][2], s2v[i][3]));
                mx = fmaxf(mx, __shfl_xor_sync(0xffffffffu, mx, 8, 16));
                mx = fmaxf(mx, __shfl_xor_sync(0xffffffffu, mx, 4, 16));
                mx = fmaxf(mx, __shfl_xor_sync(0xffffffffu, mx, 2, 16));
                mx = fmaxf(mx, __shfl_xor_sync(0xffffffffu, mx, 1, 16));
                float mn = fmaxf(m2[i], mx);
                float sc = __expf(m2[i] - mn);
                m2[i] = mn;
                float rs = 0.f;
                #pragma unroll
                for (int j = 0; j < 4; j++) {
                    float p = __expf(s2v[i][j] - mn);
                    s2v[i][j] = p;
                    rs += p;
                }
                rs += __shfl_xor_sync(0xffffffffu, rs, 8, 16);
                rs += __shfl_xor_sync(0xffffffffu, rs, 4, 16);
                rs += __shfl_xor_sync(0xffffffffu, rs, 2, 16);
                rs += __shfl_xor_sync(0xffffffffu, rs, 1, 16);
                l2[i] = l2[i] * sc + rs;
                acc2[i][0] *= sc; acc2[i][1] *= sc; acc2[i][2] *= sc; acc2[i][3] *= sc;
            }
        }

        // --- stage P tiles through smem ---
        #pragma unroll
        for (int i = 0; i < 4; i++) {
            *(float4*)&P1[((ty << 2) + i) * 64 + (tx << 2)] =
                make_float4(s1v[i][0], s1v[i][1], s1v[i][2], s1v[i][3]);
            *(float4*)&P2[((ty << 2) + i) * 64 + (tx << 2)] =
                make_float4(s2v[i][0], s2v[i][1], s2v[i][2], s2v[i][3]);
        }
        __syncthreads();

        // --- P @ V accumulation (thread owns t rows ty*4.., d dims tx*4..) ---
        #pragma unroll 8
        for (int n = 0; n < 64; n++) {
            float4 vv = *(const float4*)&Vs[n * 64 + (tx << 2)];
            #pragma unroll
            for (int i = 0; i < 4; i++) {
                float p1 = P1[((ty << 2) + i) * 64 + n];
                float p2 = P2[((ty << 2) + i) * 64 + n];
                acc1[i][0] += p1 * vv.x; acc1[i][1] += p1 * vv.y;
                acc1[i][2] += p1 * vv.z; acc1[i][3] += p1 * vv.w;
                acc2[i][0] += p2 * vv.x; acc2[i][1] += p2 * vv.y;
                acc2[i][2] += p2 * vv.z; acc2[i][3] += p2 * vv.w;
            }
        }
        __syncthreads();
    }

    // --- finalize: out = acc1/l1 - lam * acc2/l2 ---
    const float lam = sm[SM_LAM];
    #pragma unroll
    for (int i = 0; i < 4; i++) {
        float inv1 = 1.0f / l1[i];
        float inv2 = lam / l2[i];
        float4 r;
        r.x = acc1[i][0] * inv1 - acc2[i][0] * inv2;
        r.y = acc1[i][1] * inv1 - acc2[i][1] * inv2;
        r.z = acc1[i][2] * inv1 - acc2[i][2] * inv2;
        r.w = acc1[i][3] * inv1 - acc2[i][3] * inv2;
        *(float4*)&out[((size_t)(b * T_ + t0 + (ty << 2) + i)) * HID_ + h * 64 + (tx << 2)] = r;
    }
}

// ---------------------------------------------------------------------------
// Launch
// ---------------------------------------------------------------------------
extern "C" void kernel_launch(void* const* d_in, const int* in_sizes, int n_in,
                              void* d_out, int out_size)
{
    (void)in_sizes; (void)n_in; (void)out_size;
    const float* enc = (const float*)d_in[0];   // [B, N, ENC]
    const float* dec = (const float*)d_in[1];   // [B, T, DEC]
    const float* Wq  = (const float*)d_in[2];   // [HID, DEC]
    const float* Wk  = (const float*)d_in[3];   // [HID, ENC]
    const float* Wv  = (const float*)d_in[4];   // [HID, ENC]
    const float* lq1 = (const float*)d_in[5];
    const float* lq2 = (const float*)d_in[6];
    const float* lk1 = (const float*)d_in[7];
    const float* lk2 = (const float*)d_in[8];
    float* out = (float*)d_out;

    // Projections: rows = B*T = B*N = 4096
    dim3 gg(HID_ / 64, (B_ * T_) / 64);
    gemm_xwT_kernel<<<gg, 256>>>(dec, Wq, 0);   // Q
    gemm_xwT_kernel<<<gg, 256>>>(enc, Wk, 1);   // K
    gemm_xwT_kernel<<<gg, 256>>>(enc, Wv, 2);   // V

    // Attention
    const size_t smem_bytes = (size_t)SM_FLOATS * sizeof(float);
    cudaFuncSetAttribute(diff_attn_kernel,
                         cudaFuncAttributeMaxDynamicSharedMemorySize,
                         (int)smem_bytes);
    dim3 ag(T_ / 64, HEADS_, B_);
    diff_attn_kernel<<<ag, 256, smem_bytes>>>(lq1, lq2, lk1, lk2, out);
}

// round 6
// speedup vs baseline: 2.8733x; 2.8733x over previous
#include <cuda_runtime.h>
#include <math.h>
#include <stdint.h>

// Problem constants
#define B_    2
#define N_    2048
#define T_    2048
#define HID_  1024
#define HEADS_ 16
#define HALF_ 32
#define LAMBDA_INIT_ 0.8f

// Scratch for Q, K, V projections. __device__ globals: allowed scratch.
__device__ float g_q[(size_t)B_ * T_ * HID_];
__device__ float g_k[(size_t)B_ * N_ * HID_];
__device__ float g_v[(size_t)B_ * N_ * HID_];

// ---------------------------------------------------------------------------
// Helpers: tf32 conversion + m16n8k8 tf32 mma.sync (HMMA fallback path; the
// harness targets plain sm_103, so tcgen05/'a'-features are unavailable).
// ---------------------------------------------------------------------------
__device__ __forceinline__ uint32_t f2tf(float x) {
    uint32_t r;
    asm("cvt.rna.tf32.f32 %0, %1;" : "=r"(r) : "f"(x));
    return r;
}
__device__ __forceinline__ float f2tf_f(float x) { return __uint_as_float(f2tf(x)); }

__device__ __forceinline__ void mma8(float* d, const uint32_t* a, uint32_t b0, uint32_t b1) {
    asm volatile(
        "mma.sync.aligned.m16n8k8.row.col.f32.tf32.tf32.f32 "
        "{%0,%1,%2,%3},{%4,%5,%6,%7},{%8,%9},{%0,%1,%2,%3};"
        : "+f"(d[0]), "+f"(d[1]), "+f"(d[2]), "+f"(d[3])
        : "r"(a[0]), "r"(a[1]), "r"(a[2]), "r"(a[3]), "r"(b0), "r"(b1));
}

__device__ __forceinline__ uint32_t fbits(float x) { return __float_as_uint(x); }

// ---------------------------------------------------------------------------
// GEMM (tf32 mma.sync): C[4096,1024] = X[4096,1024] @ W[1024,1024]^T
// Block tile 128(M) x 128(N), k-chunks of 32. 8 warps: 4(M) x 2(N),
// warp tile 32x64. A/B staged in smem with stride-36 padding
// (fragment LDS bank-conflict-free: (36*row + col) % 32 = 4*row_g + col_t).
// ---------------------------------------------------------------------------
__global__ __launch_bounds__(256, 2) void gemm_tc_kernel(
    const float* __restrict__ X, const float* __restrict__ W, int which)
{
    __shared__ float As[128 * 36];
    __shared__ float Bs[128 * 36];

    float* __restrict__ C = (which == 0) ? g_q : (which == 1) ? g_k : g_v;

    const int tid = threadIdx.x;
    const int lane = tid & 31;
    const int wid = tid >> 5;
    const int g = lane >> 2;       // 0..7
    const int t4 = lane & 3;       // 0..3
    const int wm = wid & 3;        // warp M index (0..3)
    const int wn = wid >> 2;       // warp N index (0..1)
    const int m0 = blockIdx.y * 128;
    const int o0 = blockIdx.x * 128;

    const int lr = tid >> 3;             // 0..31
    const int lc4 = (tid & 7) << 2;      // 0,4,...,28

    float acc[2][8][4];
    #pragma unroll
    for (int mt = 0; mt < 2; mt++)
        #pragma unroll
        for (int j = 0; j < 8; j++)
            #pragma unroll
            for (int c = 0; c < 4; c++) acc[mt][j][c] = 0.f;

    const float* Xp = X + (size_t)m0 * 1024;
    const float* Wp = W + (size_t)o0 * 1024;

    float4 ra[4], rb[4];
    #pragma unroll
    for (int i = 0; i < 4; i++) {
        ra[i] = *(const float4*)(Xp + (size_t)(lr + 32 * i) * 1024 + lc4);
        rb[i] = *(const float4*)(Wp + (size_t)(lr + 32 * i) * 1024 + lc4);
    }

    for (int kc = 0; kc < 32; kc++) {
        __syncthreads();   // previous chunk's fragment reads complete
        #pragma unroll
        for (int i = 0; i < 4; i++) {
            int row = lr + 32 * i;
            float4 a = ra[i];
            *(float4*)&As[row * 36 + lc4] =
                make_float4(f2tf_f(a.x), f2tf_f(a.y), f2tf_f(a.z), f2tf_f(a.w));
            float4 b = rb[i];
            *(float4*)&Bs[row * 36 + lc4] =
                make_float4(f2tf_f(b.x), f2tf_f(b.y), f2tf_f(b.z), f2tf_f(b.w));
        }
        __syncthreads();

        if (kc < 31) {
            const float* Xn = Xp + (kc + 1) * 32;
            const float* Wn = Wp + (kc + 1) * 32;
            #pragma unroll
            for (int i = 0; i < 4; i++) {
                ra[i] = *(const float4*)(Xn + (size_t)(lr + 32 * i) * 1024 + lc4);
                rb[i] = *(const float4*)(Wn + (size_t)(lr + 32 * i) * 1024 + lc4);
            }
        }

        #pragma unroll
        for (int ks = 0; ks < 4; ks++) {
            uint32_t af[2][4];
            #pragma unroll
            for (int mt = 0; mt < 2; mt++) {
                int r0 = wm * 32 + mt * 16 + g;
                af[mt][0] = fbits(As[r0 * 36 + 8 * ks + t4]);
                af[mt][1] = fbits(As[(r0 + 8) * 36 + 8 * ks + t4]);
                af[mt][2] = fbits(As[r0 * 36 + 8 * ks + t4 + 4]);
                af[mt][3] = fbits(As[(r0 + 8) * 36 + 8 * ks + t4 + 4]);
            }
            #pragma unroll
            for (int j = 0; j < 8; j++) {
                int nr = wn * 64 + 8 * j + g;
                uint32_t b0 = fbits(Bs[nr * 36 + 8 * ks + t4]);
                uint32_t b1 = fbits(Bs[nr * 36 + 8 * ks + t4 + 4]);
                mma8(acc[0][j], af[0], b0, b1);
                mma8(acc[1][j], af[1], b0, b1);
            }
        }
    }

    // Epilogue: c0=(row, 2t), c1=(row, 2t+1), c2/c3 = row+8
    #pragma unroll
    for (int mt = 0; mt < 2; mt++)
        #pragma unroll
        for (int j = 0; j < 8; j++) {
            int row = m0 + wm * 32 + mt * 16 + g;
            int col = o0 + wn * 64 + 8 * j + 2 * t4;
            *(float2*)&C[(size_t)row * 1024 + col] =
                make_float2(acc[mt][j][0], acc[mt][j][1]);
            *(float2*)&C[(size_t)(row + 8) * 1024 + col] =
                make_float2(acc[mt][j][2], acc[mt][j][3]);
        }
}

// ---------------------------------------------------------------------------
// Differential flash attention on tf32 mma.sync.
// Grid (T/64, HEADS, B), 256 threads = 8 warps.
// Warps 0-3: S1 = Q[:,0:32]@K[:,0:32]^T, 16 rows each (warp-local softmax);
// warps 4-7: S2. P staged via warp-private smem rows; PV via mma (k=64).
// Final: warps 4-7 stage acc2/l2; warps 0-3 combine and store.
// smem layout (floats, stride 72 rows -> all fragment LDS conflict-free):
//   Qs[64][72], Ks[64][72], Vs[64][72], P1[64][72], P2[64][72], lam
// ---------------------------------------------------------------------------
#define ATT_QS 0
#define ATT_KS 4608
#define ATT_VS 9216
#define ATT_P1 13824
#define ATT_P2 18432
#define ATT_LAM 23040
#define ATT_FLOATS 23044

__global__ __launch_bounds__(256, 2) void diff_attn_kernel(
    const float* __restrict__ lq1, const float* __restrict__ lq2,
    const float* __restrict__ lk1, const float* __restrict__ lk2,
    float* __restrict__ out)
{
    extern __shared__ float sm[];
    float* Qs = sm + ATT_QS;
    float* Ks = sm + ATT_KS;
    float* Vs = sm + ATT_VS;

    const int tid = threadIdx.x;
    const int lane = tid & 31;
    const int wid = tid >> 5;
    const int g = lane >> 2;
    const int t4 = lane & 3;
    const int half = wid >> 2;          // 0: att1, 1: att2
    const int wrow = (wid & 3) * 16;    // warp's 16 S rows
    const int t0 = blockIdx.x * 64;
    const int h = blockIdx.y;
    const int b = blockIdx.z;

    float* Pw = sm + (half ? ATT_P2 : ATT_P1);   // this warp-group's P region

    if (tid == 0) {
        float s1 = 0.f, s2 = 0.f;
        #pragma unroll
        for (int i = 0; i < HALF_; i++) {
            s1 += lq1[i] * lk1[i];
            s2 += lq2[i] * lk2[i];
        }
        sm[ATT_LAM] = expf(s1) - expf(s2) + LAMBDA_INIT_;
    }

    const float scale = 0.17677669529663687f;   // 1/sqrt(32)

    // Load Q tile (pre-scaled, tf32-rounded)
    {
        const float* qb = g_q + ((size_t)(b * T_ + t0)) * HID_ + h * 64;
        #pragma unroll
        for (int i = 0; i < 4; i++) {
            int idx = tid + i * 256;
            int r = idx >> 4, c4 = (idx & 15) << 2;
            float4 v = *(const float4*)&qb[(size_t)r * HID_ + c4];
            *(float4*)&Qs[r * 72 + c4] = make_float4(
                f2tf_f(v.x * scale), f2tf_f(v.y * scale),
                f2tf_f(v.z * scale), f2tf_f(v.w * scale));
        }
    }

    float acc[8][4];
    #pragma unroll
    for (int j = 0; j < 8; j++)
        #pragma unroll
        for (int c = 0; c < 4; c++) acc[j][c] = 0.f;
    float mrow[2] = { -1e30f, -1e30f };
    float lrow[2] = { 0.f, 0.f };

    const float* kb0 = g_k + ((size_t)(b * N_)) * HID_ + h * 64;
    const float* vb0 = g_v + ((size_t)(b * N_)) * HID_ + h * 64;
    const int ldr = tid >> 4;                 // 0..15 (base row)
    const int ldc4 = (tid & 15) << 2;         // 0..60

    // register prefetch of first K/V tile (overlaps Q staging)
    float4 pk[4], pv[4];
    #pragma unroll
    for (int i = 0; i < 4; i++) {
        int r = ldr + 16 * i;
        pk[i] = *(const float4*)&kb0[(size_t)r * HID_ + ldc4];
        pv[i] = *(const float4*)&vb0[(size_t)r * HID_ + ldc4];
    }

    for (int nt = 0; nt < N_ / 64; nt++) {
        __syncthreads();   // all fragment reads of Ks/Vs from prev iter done
        #pragma unroll
        for (int i = 0; i < 4; i++) {
            int r = ldr + 16 * i;
            float4 kv = pk[i];
            *(float4*)&Ks[r * 72 + ldc4] = make_float4(
                f2tf_f(kv.x), f2tf_f(kv.y), f2tf_f(kv.z), f2tf_f(kv.w));
            float4 vv = pv[i];
            *(float4*)&Vs[r * 72 + ldc4] = make_float4(
                f2tf_f(vv.x), f2tf_f(vv.y), f2tf_f(vv.z), f2tf_f(vv.w));
        }
        __syncthreads();

        // prefetch next tile (overlaps this tile's MMA work)
        if (nt < N_ / 64 - 1) {
            const float* kb = kb0 + (size_t)(nt + 1) * 64 * HID_;
            const float* vb = vb0 + (size_t)(nt + 1) * 64 * HID_;
            #pragma unroll
            for (int i = 0; i < 4; i++) {
                int r = ldr + 16 * i;
                pk[i] = *(const float4*)&kb[(size_t)r * HID_ + ldc4];
                pv[i] = *(const float4*)&vb[(size_t)r * HID_ + ldc4];
            }
        }

        // ---- S = Q_half @ K_half^T : 16 rows x 64 cols per warp ----
        float s[8][4];
        #pragma unroll
        for (int j = 0; j < 8; j++)
            #pragma unroll
            for (int c = 0; c < 4; c++) s[j][c] = 0.f;

        const int dbase = half * 32;
        #pragma unroll
        for (int ks = 0; ks < 4; ks++) {
            uint32_t af[4];
            int r0 = wrow + g;
            af[0] = fbits(Qs[r0 * 72 + dbase + 8 * ks + t4]);
            af[1] = fbits(Qs[(r0 + 8) * 72 + dbase + 8 * ks + t4]);
            af[2] = fbits(Qs[r0 * 72 + dbase + 8 * ks + t4 + 4]);
            af[3] = fbits(Qs[(r0 + 8) * 72 + dbase + 8 * ks + t4 + 4]);
            #pragma unroll
            for (int j = 0; j < 8; j++) {
                int nr = 8 * j + g;
                uint32_t b0 = fbits(Ks[nr * 72 + dbase + 8 * ks + t4]);
                uint32_t b1 = fbits(Ks[nr * 72 + dbase + 8 * ks + t4 + 4]);
                mma8(s[j], af, b0, b1);
            }
        }

        // ---- warp-local online softmax (rows g and g+8) ----
        #pragma unroll
        for (int r = 0; r < 2; r++) {
            float mx = -1e30f;
            #pragma unroll
            for (int j = 0; j < 8; j++)
                mx = fmaxf(mx, fmaxf(s[j][2 * r], s[j][2 * r + 1]));
            mx = fmaxf(mx, __shfl_xor_sync(0xffffffffu, mx, 1));
            mx = fmaxf(mx, __shfl_xor_sync(0xffffffffu, mx, 2));
            float mn = fmaxf(mrow[r], mx);
            float sc = __expf(mrow[r] - mn);
            mrow[r] = mn;
            float rs = 0.f;
            #pragma unroll
            for (int j = 0; j < 8; j++) {
                float p0 = __expf(s[j][2 * r] - mn);
                float p1 = __expf(s[j][2 * r + 1] - mn);
                s[j][2 * r] = p0;
                s[j][2 * r + 1] = p1;
                rs += p0 + p1;
            }
            rs += __shfl_xor_sync(0xffffffffu, rs, 1);
            rs += __shfl_xor_sync(0xffffffffu, rs, 2);
            lrow[r] = lrow[r] * sc + rs;
            #pragma unroll
            for (int j = 0; j < 8; j++) {
                acc[j][2 * r] *= sc;
                acc[j][2 * r + 1] *= sc;
            }
        }

        // ---- stage P (warp-private rows; tf32-rounded) ----
        #pragma unroll
        for (int r = 0; r < 2; r++)
            #pragma unroll
            for (int j = 0; j < 8; j++)
                *(float2*)&Pw[(wrow + g + 8 * r) * 72 + 8 * j + 2 * t4] =
                    make_float2(f2tf_f(s[j][2 * r]), f2tf_f(s[j][2 * r + 1]));
        __syncwarp();

        // ---- acc += P @ V : 16 rows x 64 d per warp, k = 64 ----
        #pragma unroll
        for (int ks = 0; ks < 8; ks++) {
            uint32_t af[4];
            int r0 = wrow + g;
            af[0] = fbits(Pw[r0 * 72 + 8 * ks + t4]);
            af[1] = fbits(Pw[(r0 + 8) * 72 + 8 * ks + t4]);
            af[2] = fbits(Pw[r0 * 72 + 8 * ks + t4 + 4]);
            af[3] = fbits(Pw[(r0 + 8) * 72 + 8 * ks + t4 + 4]);
            #pragma unroll
            for (int j = 0; j < 8; j++) {
                uint32_t b0 = fbits(Vs[(8 * ks + t4) * 72 + 8 * j + g]);
                uint32_t b1 = fbits(Vs[(8 * ks + t4 + 4) * 72 + 8 * j + g]);
                mma8(acc[j], af, b0, b1);
            }
        }
    }

    __syncthreads();
    const float lam = sm[ATT_LAM];

    if (half == 1) {
        // stage acc2 / l2 into P2 region (warp-private rows)
        float* St = sm + ATT_P2;
        #pragma unroll
        for (int r = 0; r < 2; r++) {
            float inv = 1.0f / lrow[r];
            #pragma unroll
            for (int j = 0; j < 8; j++)
                *(float2*)&St[(wrow + g + 8 * r) * 72 + 8 * j + 2 * t4] =
                    make_float2(acc[j][2 * r] * inv, acc[j][2 * r + 1] * inv);
        }
    }
    __syncthreads();
    if (half == 0) {
        const float* St = sm + ATT_P2;
        #pragma unroll
        for (int r = 0; r < 2; r++) {
            float inv = 1.0f / lrow[r];
            int row = wrow + g + 8 * r;
            #pragma unroll
            for (int j = 0; j < 8; j++) {
                float2 o2 = *(const float2*)&St[row * 72 + 8 * j + 2 * t4];
                float2 res;
                res.x = acc[j][2 * r] * inv - lam * o2.x;
                res.y = acc[j][2 * r + 1] * inv - lam * o2.y;
                *(float2*)&out[((size_t)(b * T_ + t0 + row)) * HID_ + h * 64 + 8 * j + 2 * t4] = res;
            }
        }
    }
}

// ---------------------------------------------------------------------------
// Launch
// ---------------------------------------------------------------------------
extern "C" void kernel_launch(void* const* d_in, const int* in_sizes, int n_in,
                              void* d_out, int out_size)
{
    (void)in_sizes; (void)n_in; (void)out_size;
    const float* enc = (const float*)d_in[0];   // [B, N, ENC]
    const float* dec = (const float*)d_in[1];   // [B, T, DEC]
    const float* Wq  = (const float*)d_in[2];   // [HID, DEC]
    const float* Wk  = (const float*)d_in[3];   // [HID, ENC]
    const float* Wv  = (const float*)d_in[4];   // [HID, ENC]
    const float* lq1 = (const float*)d_in[5];
    const float* lq2 = (const float*)d_in[6];
    const float* lk1 = (const float*)d_in[7];
    const float* lk2 = (const float*)d_in[8];
    float* out = (float*)d_out;

    dim3 gg(HID_ / 128, (B_ * T_) / 128);
    gemm_tc_kernel<<<gg, 256>>>(dec, Wq, 0);   // Q
    gemm_tc_kernel<<<gg, 256>>>(enc, Wk, 1);   // K
    gemm_tc_kernel<<<gg, 256>>>(enc, Wv, 2);   // V

    const size_t smem_bytes = (size_t)ATT_FLOATS * sizeof(float);
    cudaFuncSetAttribute(diff_attn_kernel,
                         cudaFuncAttributeMaxDynamicSharedMemorySize,
                         (int)smem_bytes);
    dim3 ag(T_ / 64, HEADS_, B_);
    diff_attn_kernel<<<ag, 256, smem_bytes>>>(lq1, lq2, lk1, lk2, out);
}